// round 1
// baseline (speedup 1.0000x reference)
#include <cuda_runtime.h>

#define N 8192
#define D 128
#define RB 64              // rows per CTA
#define CT 128             // cols per tile
#define CSPLIT 2           // column split across CTAs
#define CPC (N / CSPLIT)   // 4096 cols per CTA
#define NT (CPC / CT)      // 32 tiles
#define APAD 68            // padded A-tile row stride (floats), 16B aligned, conflict-spread
#define BPAD 132           // padded B-tile row stride

__device__ float g_sq[N];
__device__ float g_topD[CSPLIT * N * 5];
__device__ int   g_topI[CSPLIT * N * 5];
__device__ float g_hinge[N];

__device__ __forceinline__ bool better(float d1, int i1, float d2, int i2) {
    // smaller distance wins; ties broken by smaller index (matches jax top_k)
    return (d1 < d2) || (d1 == d2 && i1 < i2);
}

// ---------------------------------------------------------------------------
// Kernel A: row squared norms
// ---------------------------------------------------------------------------
__global__ void sq_kernel(const float* __restrict__ x) {
    int row  = blockIdx.x * 8 + (threadIdx.x >> 5);
    int lane = threadIdx.x & 31;
    const float* xr = x + row * D;
    float s = 0.f;
#pragma unroll
    for (int k = 0; k < 4; k++) {
        float v = xr[lane + 32 * k];
        s = fmaf(v, v, s);
    }
#pragma unroll
    for (int o = 16; o; o >>= 1) s += __shfl_xor_sync(0xffffffffu, s, o);
    if (lane == 0) g_sq[row] = s;
}

// ---------------------------------------------------------------------------
// Kernel B: fused Gram tile + per-row top-5 (by clamped squared distance)
// Grid: (CSPLIT, N/RB). 256 threads as 16(tx) x 16(ty); each thread owns a
// 4-row x 8-col micro-tile. Thread-local sorted top-5 per row, merged across
// the 16 column-threads of a row group with half-warp butterfly shuffles.
// ---------------------------------------------------------------------------
extern __shared__ float smem[];

__global__ __launch_bounds__(256) void dist_top5_kernel(const float* __restrict__ x) {
    float* As = smem;              // [D][APAD], [k][r], r < RB
    float* Bs = smem + D * APAD;   // [D][BPAD], [k][c], c < CT

    const int bx = blockIdx.x;     // column split
    const int by = blockIdx.y;     // row block
    const int tid = threadIdx.x;
    const int tx = tid & 15;
    const int ty = tid >> 4;
    const int rowBase = by * RB;
    const int r0 = rowBase + ty * 4;

    // Load A tile once (coalesced global, conflict-spread shared writes)
    for (int i = tid; i < RB * D; i += 256) {
        int k = i & (D - 1), r = i >> 7;
        As[k * APAD + r] = x[(rowBase + r) * D + k];
    }

    float sqR[4];
#pragma unroll
    for (int r = 0; r < 4; r++) sqR[r] = g_sq[r0 + r];

    float t5d[4][5];
    int   t5i[4][5];
#pragma unroll
    for (int r = 0; r < 4; r++)
#pragma unroll
        for (int s = 0; s < 5; s++) {
            t5d[r][s] = __int_as_float(0x7f800000);  // +inf
            t5i[r][s] = 0x7fffffff;
        }

    for (int t = 0; t < NT; t++) {
        const int colBase = bx * CPC + t * CT;
        __syncthreads();   // previous tile's consumers done (also covers A on t=0)
        for (int i = tid; i < CT * D; i += 256) {
            int k = i & (D - 1), c = i >> 7;
            Bs[k * BPAD + c] = x[(colBase + c) * D + k];
        }
        __syncthreads();

        float acc[4][8];
#pragma unroll
        for (int r = 0; r < 4; r++)
#pragma unroll
            for (int c = 0; c < 8; c++) acc[r][c] = 0.f;

#pragma unroll 8
        for (int k = 0; k < D; k++) {
            float4 a  = *(const float4*)&As[k * APAD + ty * 4];
            float4 b0 = *(const float4*)&Bs[k * BPAD + tx * 8];
            float4 b1 = *(const float4*)&Bs[k * BPAD + tx * 8 + 4];
            float av[4] = {a.x, a.y, a.z, a.w};
            float bv[8] = {b0.x, b0.y, b0.z, b0.w, b1.x, b1.y, b1.z, b1.w};
#pragma unroll
            for (int r = 0; r < 4; r++)
#pragma unroll
                for (int c = 0; c < 8; c++)
                    acc[r][c] = fmaf(av[r], bv[c], acc[r][c]);
        }

        // Candidate insertion (ascending j per thread -> stable tie handling)
#pragma unroll
        for (int c = 0; c < 8; c++) {
            int j = colBase + tx * 8 + c;
            float sqC = g_sq[j];
#pragma unroll
            for (int r = 0; r < 4; r++) {
                float d2 = fmaf(-2.f, acc[r][c], sqR[r] + sqC);
                d2 = fmaxf(d2, 1e-12f);
                if (better(d2, j, t5d[r][4], t5i[r][4])) {
                    float cd = d2; int ci = j;
#pragma unroll
                    for (int s = 0; s < 5; s++) {
                        if (better(cd, ci, t5d[r][s], t5i[r][s])) {
                            float td = t5d[r][s]; t5d[r][s] = cd; cd = td;
                            int   ti = t5i[r][s]; t5i[r][s] = ci; ci = ti;
                        }
                    }
                }
            }
        }
    }

    // Butterfly merge across the 16 threads (a half-warp) sharing each row group
#pragma unroll
    for (int r = 0; r < 4; r++) {
#pragma unroll
        for (int off = 1; off < 16; off <<= 1) {
            float od[5]; int oi[5];
#pragma unroll
            for (int s = 0; s < 5; s++) {
                od[s] = __shfl_xor_sync(0xffffffffu, t5d[r][s], off);
                oi[s] = __shfl_xor_sync(0xffffffffu, t5i[r][s], off);
            }
            float ad[5]; int ai[5];
#pragma unroll
            for (int s = 0; s < 5; s++) { ad[s] = t5d[r][s]; ai[s] = t5i[r][s]; }
            int ia = 0, ib = 0;
#pragma unroll
            for (int s = 0; s < 5; s++) {
                bool ta = better(ad[ia], ai[ia], od[ib], oi[ib]);
                t5d[r][s] = ta ? ad[ia] : od[ib];
                t5i[r][s] = ta ? ai[ia] : oi[ib];
                if (ta) ia++; else ib++;
            }
        }
    }

    if (tx == 0) {
#pragma unroll
        for (int r = 0; r < 4; r++) {
            int row = r0 + r;
#pragma unroll
            for (int s = 0; s < 5; s++) {
                g_topD[(bx * N + row) * 5 + s] = t5d[r][s];
                g_topI[(bx * N + row) * 5 + s] = t5i[r][s];
            }
        }
    }
}

// ---------------------------------------------------------------------------
// Kernel C: merge the CSPLIT partial top-5 lists, pick 5th-smallest index,
// compute the per-row hinge term. One warp per row.
// ---------------------------------------------------------------------------
__global__ void finalize_kernel(const float* __restrict__ x, const float* __restrict__ p) {
    int row  = blockIdx.x * 8 + (threadIdx.x >> 5);
    int lane = threadIdx.x & 31;
    int neg = 0;
    if (lane == 0) {
        float ad[5], bd[5]; int ai[5], bi[5];
#pragma unroll
        for (int s = 0; s < 5; s++) {
            ad[s] = g_topD[(0 * N + row) * 5 + s]; ai[s] = g_topI[(0 * N + row) * 5 + s];
            bd[s] = g_topD[(1 * N + row) * 5 + s]; bi[s] = g_topI[(1 * N + row) * 5 + s];
        }
        int ia = 0, ib = 0;
#pragma unroll
        for (int s = 0; s < 5; s++) {
            bool ta = better(ad[ia], ai[ia], bd[ib], bi[ib]);
            neg = ta ? ai[ia] : bi[ib];
            if (ta) ia++; else ib++;
        }
    }
    neg = __shfl_sync(0xffffffffu, neg, 0);

    const float* xr = x + row * D;
    const float* pr = p + row * D;
    const float* nr = x + neg * D;
    float sap = 0.f, san = 0.f;
#pragma unroll
    for (int kk = 0; kk < 4; kk++) {
        int k = lane + 32 * kk;
        float xv = xr[k];
        float dp = xv - pr[k] + 1e-6f;
        float dn = xv - nr[k] + 1e-6f;
        sap = fmaf(dp, dp, sap);
        san = fmaf(dn, dn, san);
    }
#pragma unroll
    for (int o = 16; o; o >>= 1) {
        sap += __shfl_xor_sync(0xffffffffu, sap, o);
        san += __shfl_xor_sync(0xffffffffu, san, o);
    }
    if (lane == 0)
        g_hinge[row] = fmaxf(sqrtf(sap) - sqrtf(san) + 0.3f, 0.f);
}

// ---------------------------------------------------------------------------
// Kernel D: deterministic fixed-schedule mean
// ---------------------------------------------------------------------------
__global__ void reduce_kernel(float* out) {
    __shared__ float sh[256];
    int tid = threadIdx.x;
    float s = 0.f;
    for (int i = tid; i < N; i += 256) s += g_hinge[i];
    sh[tid] = s;
    __syncthreads();
    for (int o = 128; o; o >>= 1) {
        if (tid < o) sh[tid] += sh[tid + o];
        __syncthreads();
    }
    if (tid == 0) out[0] = sh[0] * (1.0f / N);
}

// ---------------------------------------------------------------------------
extern "C" void kernel_launch(void* const* d_in, const int* in_sizes, int n_in,
                              void* d_out, int out_size) {
    const float* x   = (const float*)d_in[0];   // inputs  [8192,128]
    const float* pos = (const float*)d_in[1];   // positive[8192,128]
    float* out = (float*)d_out;

    size_t smem_bytes = (size_t)(D * APAD + D * BPAD) * sizeof(float);  // 100 KB
    cudaFuncSetAttribute(dist_top5_kernel,
                         cudaFuncAttributeMaxDynamicSharedMemorySize,
                         (int)smem_bytes);

    sq_kernel<<<N / 8, 256>>>(x);
    dim3 grid(CSPLIT, N / RB);
    dist_top5_kernel<<<grid, 256, smem_bytes>>>(x);
    finalize_kernel<<<N / 8, 256>>>(x, pos);
    reduce_kernel<<<1, 256>>>(out);
}